// round 16
// baseline (speedup 1.0000x reference)
#include <cuda_runtime.h>
#include <cuda_bf16.h>
#include <cuda_fp16.h>
#include <cstdint>

#define NTOK 32768
#define DIM  512
#define KCB  8192

#define BM     128
#define BN     128
#define BK     64
#define NCHUNK (DIM / BK)         // 8
#define STAGES 2
#define TILE_BYTES (BM * BK * 2)  // 16384

#define THRESH   1.0f
#define CAND_MAX 256

// output layout (flat float32 concat, reference return order)
#define O_LOSS  ((size_t)0)
#define O_ZQ    ((size_t)1)
#define O_CODES ((size_t)(1 + (size_t)NTOK*DIM))
#define O_NW    ((size_t)(O_CODES + NTOK))
#define O_NCS   ((size_t)(O_NW + (size_t)KCB*DIM))
#define O_NEW   ((size_t)(O_NCS + KCB))

// ---- device scratch (static: no allocation allowed) ----
__device__ __align__(16) __nv_bfloat16 g_A[(size_t)NTOK * DIM];    // 32 MB
__device__ __align__(16) __nv_bfloat16 g_B[(size_t)KCB  * DIM];    // 8 MB
__device__ __align__(16) __half g_metric[(size_t)NTOK * KCB];      // 512 MB
__device__ int   g_codes[NTOK];
__device__ float g_wn[KCB];
__device__ float g_loss;
__device__ float g_nsum;

// ---------------------------------------------------------------------------
// PTX helpers (sm_80-era only: supported at base sm_103 PTX target)
// ---------------------------------------------------------------------------
__device__ __forceinline__ uint32_t smem_u32(const void* p) {
    uint32_t a;
    asm("{ .reg .u64 t; cvta.to.shared.u64 t, %1; cvt.u32.u64 %0, t; }" : "=r"(a) : "l"(p));
    return a;
}
__device__ __forceinline__ void cp16(uint32_t s, const void* g) {
    asm volatile("cp.async.cg.shared.global [%0], [%1], 16;" :: "r"(s), "l"(g));
}
#define CP_COMMIT() asm volatile("cp.async.commit_group;" ::: "memory")
#define CP_WAIT(n)  asm volatile("cp.async.wait_group %0;" :: "n"(n) : "memory")

__device__ __forceinline__ void ldsm4(uint32_t& r0, uint32_t& r1, uint32_t& r2, uint32_t& r3,
                                      uint32_t addr) {
    asm volatile("ldmatrix.sync.aligned.m8n8.x4.shared.b16 {%0,%1,%2,%3}, [%4];"
                 : "=r"(r0), "=r"(r1), "=r"(r2), "=r"(r3) : "r"(addr));
}
__device__ __forceinline__ void mma16816(float* d, uint32_t a0, uint32_t a1, uint32_t a2,
                                         uint32_t a3, uint32_t b0, uint32_t b1) {
    asm volatile(
        "mma.sync.aligned.m16n8k16.row.col.f32.bf16.bf16.f32 "
        "{%0,%1,%2,%3},{%4,%5,%6,%7},{%8,%9},{%0,%1,%2,%3};"
        : "+f"(d[0]), "+f"(d[1]), "+f"(d[2]), "+f"(d[3])
        : "r"(a0), "r"(a1), "r"(a2), "r"(a3), "r"(b0), "r"(b1));
}

// ---------------------------------------------------------------------------
// init
// ---------------------------------------------------------------------------
__global__ void init_kernel(const float* __restrict__ ema_w,
                            const float* __restrict__ ema_cs,
                            float* __restrict__ out) {
    int idx = blockIdx.x * blockDim.x + threadIdx.x;
    if (idx < KCB * DIM) out[O_NEW + idx] = 0.99f * ema_w[idx];
    if (idx < KCB)       out[O_NCS + idx] = 0.99f * ema_cs[idx];
    if (idx == 0) { g_loss = 0.0f; g_nsum = 0.0f; }
}

// ---------------------------------------------------------------------------
// wn + conv_w fused: one warp per weight row computes 0.5||w||^2 AND writes
// the bf16 copy (data already in registers; coalesced 8B stores)
// ---------------------------------------------------------------------------
__global__ void wnconv_kernel(const float* __restrict__ weight,
                              __nv_bfloat16* __restrict__ dstB) {
    int gw = (blockIdx.x * blockDim.x + threadIdx.x) >> 5;
    int lane = threadIdx.x & 31;
    if (gw >= KCB) return;
    const float4* row = (const float4*)(weight + (size_t)gw * DIM);
    __nv_bfloat16* drow = dstB + (size_t)gw * DIM;
    float s = 0.0f;
#pragma unroll
    for (int p = 0; p < 4; p++) {
        float4 v = row[p * 32 + lane];
        s += v.x * v.x + v.y * v.y + v.z * v.z + v.w * v.w;
        __nv_bfloat16 h[4] = {__float2bfloat16(v.x), __float2bfloat16(v.y),
                              __float2bfloat16(v.z), __float2bfloat16(v.w)};
        *(uint2*)(drow + p * 128 + lane * 4) = *(uint2*)h;
    }
#pragma unroll
    for (int o = 16; o > 0; o >>= 1) s += __shfl_xor_sync(0xffffffffu, s, o);
    if (lane == 0) g_wn[gw] = 0.5f * s;
}

// ---------------------------------------------------------------------------
// convert fp32 -> bf16 (z operand)
// ---------------------------------------------------------------------------
__global__ void conv_kernel(const float* __restrict__ src, __nv_bfloat16* __restrict__ dst,
                            int n8) {
    int idx = blockIdx.x * blockDim.x + threadIdx.x;
    if (idx >= n8) return;
    const float4* s4 = (const float4*)src + (size_t)idx * 2;
    float4 a = s4[0], b = s4[1];
    __nv_bfloat16 h[8] = {
        __float2bfloat16(a.x), __float2bfloat16(a.y), __float2bfloat16(a.z), __float2bfloat16(a.w),
        __float2bfloat16(b.x), __float2bfloat16(b.y), __float2bfloat16(b.z), __float2bfloat16(b.w)};
    *(uint4*)(dst + (size_t)idx * 8) = *(uint4*)h;
}

// ---------------------------------------------------------------------------
// coarse bf16 GEMM: metric[t][k] = dot_bf16(z_t, w_k) - 0.5||w_k||^2 -> fp16
// grid (KCB/BN = 64 fast, NTOK/BM = 256), 256 threads
// 2-stage cp.async (66 KB smem) -> 3 CTAs/SM for latency hiding
// ---------------------------------------------------------------------------
#define SMEM_WNS   (2 * STAGES * TILE_BYTES)           // 65536
#define SMEM_BYTES (SMEM_WNS + BN * 4)                 // 66048

__device__ __forceinline__ void load_chunk(uint32_t sb, const char* gA, const char* gB,
                                           int kc, int s, int tid) {
#pragma unroll
    for (int i = 0; i < 4; i++) {
        int idx = tid + i * 256;
        int row = idx >> 3, ch = idx & 7;
        uint32_t so = (uint32_t)(s * TILE_BYTES + row * 128 + ((ch ^ (row & 7)) << 4));
        cp16(sb + so, gA + (size_t)row * (DIM * 2) + (size_t)kc * (BK * 2) + ch * 16);
    }
#pragma unroll
    for (int i = 0; i < 4; i++) {
        int idx = tid + i * 256;
        int row = idx >> 3, ch = idx & 7;
        uint32_t so = (uint32_t)(STAGES * TILE_BYTES + s * TILE_BYTES + row * 128 +
                                 ((ch ^ (row & 7)) << 4));
        cp16(sb + so, gB + (size_t)row * (DIM * 2) + (size_t)kc * (BK * 2) + ch * 16);
    }
}

__global__ void __launch_bounds__(256, 3)
coarse_mma_kernel() {
    extern __shared__ __align__(128) unsigned char smem[];
    const uint32_t sb = smem_u32(smem);
    const int tid = threadIdx.x;
    const int lane = tid & 31, wid = tid >> 5;
    const int wm = wid & 3, wn = wid >> 2;
    const int n_tile = blockIdx.x, m_tile = blockIdx.y;

    float* wns_s = (float*)(smem + SMEM_WNS);
    if (tid < BN) wns_s[tid] = g_wn[n_tile * BN + tid];

    const char* gA = (const char*)g_A + (size_t)m_tile * BM * (DIM * 2);
    const char* gB = (const char*)g_B + (size_t)n_tile * BN * (DIM * 2);

    float acc[2][8][4];
#pragma unroll
    for (int mi = 0; mi < 2; mi++)
#pragma unroll
        for (int ni = 0; ni < 8; ni++)
#pragma unroll
            for (int j = 0; j < 4; j++) acc[mi][ni][j] = 0.0f;

#pragma unroll
    for (int i = 0; i < STAGES - 1; i++) {
        load_chunk(sb, gA, gB, i, i, tid);
        CP_COMMIT();
    }

    for (int kc = 0; kc < NCHUNK; kc++) {
        const int s = kc % STAGES;
        CP_WAIT(STAGES - 2);
        __syncthreads();
        const int pf = kc + STAGES - 1;
        if (pf < NCHUNK) load_chunk(sb, gA, gB, pf, pf % STAGES, tid);
        CP_COMMIT();

        const uint32_t aBase = sb + s * TILE_BYTES;
        const uint32_t bBase = sb + (STAGES + s) * TILE_BYTES;
#pragma unroll
        for (int ks = 0; ks < 4; ks++) {
            uint32_t a[2][4];
#pragma unroll
            for (int mi = 0; mi < 2; mi++) {
                int row = wm * 32 + mi * 16 + (lane & 15);
                int ch  = ks * 2 + (lane >> 4);
                ldsm4(a[mi][0], a[mi][1], a[mi][2], a[mi][3],
                      aBase + row * 128 + ((ch ^ (row & 7)) << 4));
            }
            uint32_t b[8][2];
#pragma unroll
            for (int p = 0; p < 4; p++) {
                int l = lane & 7, sel = lane >> 3;
                int row = wn * 64 + p * 16 + (sel & 1) * 8 + l;
                int ch  = ks * 2 + (sel >> 1);
                uint32_t r0, r1, r2, r3;
                ldsm4(r0, r1, r2, r3, bBase + row * 128 + ((ch ^ (row & 7)) << 4));
                b[2 * p][0] = r0; b[2 * p][1] = r2;
                b[2 * p + 1][0] = r1; b[2 * p + 1][1] = r3;
            }
#pragma unroll
            for (int mi = 0; mi < 2; mi++)
#pragma unroll
                for (int ni = 0; ni < 8; ni++)
                    mma16816(acc[mi][ni], a[mi][0], a[mi][1], a[mi][2], a[mi][3],
                             b[ni][0], b[ni][1]);
        }
        __syncthreads();
    }

    // epilogue: store coarse metric tile as fp16 (half2, 4B-aligned)
#pragma unroll
    for (int mi = 0; mi < 2; mi++) {
#pragma unroll
        for (int r = 0; r < 2; r++) {
            int token = m_tile * BM + wm * 32 + mi * 16 + r * 8 + (lane >> 2);
            __half* rowp = g_metric + (size_t)token * KCB + n_tile * BN;
#pragma unroll
            for (int ni = 0; ni < 8; ni++) {
                int n0 = wn * 64 + ni * 8 + (lane & 3) * 2;
                __half2 v = __floats2half2_rn(acc[mi][ni][r * 2 + 0] - wns_s[n0],
                                              acc[mi][ni][r * 2 + 1] - wns_s[n0 + 1]);
                *(__half2*)(rowp + n0) = v;
            }
        }
    }
}

// ---------------------------------------------------------------------------
// scan + exact refine + fused scatter (validated R15)
// ---------------------------------------------------------------------------
__global__ void __launch_bounds__(256)
scan_refine_scatter_kernel(const float* __restrict__ z, const float* __restrict__ weight,
                           float* __restrict__ out) {
    __shared__ __half met[KCB];         // 16 KB
    __shared__ float wred[8];
    __shared__ int   cand[CAND_MAX];
    __shared__ int   ccount;
    __shared__ float wbest[8];
    __shared__ int   wbidx[8];
    __shared__ int   s_code;

    const int token = blockIdx.x;
    const int tid = threadIdx.x;
    const int lane = tid & 31, wid = tid >> 5;

    const float4* src = (const float4*)(g_metric + (size_t)token * KCB);
    float lmax = -3.4e38f;
#pragma unroll
    for (int i = 0; i < 4; i++) {
        float4 v = src[tid + i * 256];
        ((float4*)met)[tid + i * 256] = v;
        const __half2* h2 = (const __half2*)&v;
#pragma unroll
        for (int j = 0; j < 4; j++) {
            float2 f = __half22float2(h2[j]);
            lmax = fmaxf(lmax, fmaxf(f.x, f.y));
        }
    }
#pragma unroll
    for (int o = 16; o > 0; o >>= 1) lmax = fmaxf(lmax, __shfl_xor_sync(0xffffffffu, lmax, o));
    if (lane == 0) wred[wid] = lmax;
    if (tid == 0) ccount = 0;
    __syncthreads();
    float gmax = wred[0];
#pragma unroll
    for (int w = 1; w < 8; w++) gmax = fmaxf(gmax, wred[w]);
    const float thresh = gmax - THRESH;

    for (int i = tid; i < KCB; i += 256) {
        if (__half2float(met[i]) >= thresh) {
            int p = atomicAdd(&ccount, 1);
            if (p < CAND_MAX) cand[p] = i;
        }
    }
    __syncthreads();
    int nc = ccount;
    if (nc > CAND_MAX) nc = CAND_MAX;

    const float4* z4 = (const float4*)(z + (size_t)token * DIM);
    float4 zw[4];
#pragma unroll
    for (int i = 0; i < 4; i++) zw[i] = z4[lane + 32 * i];

    float best = -3.4e38f;
    int bidx = KCB;
    for (int c = wid; c < nc; c += 8) {
        int k = cand[c];
        const float4* w4 = (const float4*)(weight + (size_t)k * DIM);
        float s = 0.0f;
#pragma unroll
        for (int i = 0; i < 4; i++) {
            float4 wv = w4[lane + 32 * i];
            s += zw[i].x * wv.x + zw[i].y * wv.y + zw[i].z * wv.z + zw[i].w * wv.w;
        }
#pragma unroll
        for (int o = 16; o > 0; o >>= 1) s += __shfl_xor_sync(0xffffffffu, s, o);
        float mex = s - g_wn[k];
        if (mex > best || (mex == best && k < bidx)) { best = mex; bidx = k; }
    }
    if (lane == 0) { wbest[wid] = best; wbidx[wid] = bidx; }
    __syncthreads();
    if (tid == 0) {
        float bb = wbest[0];
        int bi = wbidx[0];
#pragma unroll
        for (int w = 1; w < 8; w++) {
            float v = wbest[w];
            int k = wbidx[w];
            if (v > bb || (v == bb && k < bi)) { bb = v; bi = k; }
        }
        s_code = bi;
        g_codes[token] = bi;
        out[O_CODES + token] = (float)bi;
        atomicAdd(out + O_NCS + bi, 0.01f);
    }
    __syncthreads();

    const int code = s_code;
    float* dst = out + O_NEW + (size_t)code * DIM;
    const float2 zv = ((const float2*)(z + (size_t)token * DIM))[tid];
    atomicAdd(dst + 2 * tid,     0.01f * zv.x);
    atomicAdd(dst + 2 * tid + 1, 0.01f * zv.y);
}

// ---------------------------------------------------------------------------
// nsum / weight / gather / finalize (validated R1..R15)
// ---------------------------------------------------------------------------
__global__ void nsum_kernel(const float* __restrict__ out) {
    __shared__ float red[1024];
    int tid = threadIdx.x;
    float s = 0.0f;
    for (int i = tid; i < KCB; i += 1024) s += out[O_NCS + i];
    red[tid] = s;
    __syncthreads();
    for (int o = 512; o > 0; o >>= 1) {
        if (tid < o) red[tid] += red[tid + o];
        __syncthreads();
    }
    if (tid == 0) g_nsum = red[0];
}

__global__ void weight_kernel(float* __restrict__ out) {
    int idx = blockIdx.x * blockDim.x + threadIdx.x;
    if (idx >= KCB * DIM) return;
    int k = idx >> 9;
    float n = g_nsum;
    float cs = (out[O_NCS + k] + 1e-5f) / (n + KCB * 1e-5f) * n;
    out[O_NW + idx] = out[O_NEW + idx] / cs;
}

__global__ void gather_kernel(const float* __restrict__ z, float* __restrict__ out) {
    __shared__ float red[128];
    int token = blockIdx.x, tid = threadIdx.x;
    int code = g_codes[token];
    const float* wr = out + O_NW + (size_t)code * DIM;
    const float* zr = z + (size_t)token * DIM;
    float* oq = out + O_ZQ + (size_t)token * DIM;
    float ls = 0.0f;
#pragma unroll
    for (int i = 0; i < 4; i++) {
        int d = i * 128 + tid;
        float w = wr[d], v = zr[d];
        float t = w - v;
        oq[d] = v + t;
        ls += t * t;
    }
    red[tid] = ls;
    __syncthreads();
    for (int o = 64; o > 0; o >>= 1) {
        if (tid < o) red[tid] += red[tid + o];
        __syncthreads();
    }
    if (tid == 0) atomicAdd(&g_loss, red[0]);
}

__global__ void finalize_kernel(float* __restrict__ out) {
    out[O_LOSS] = 0.25f * g_loss / (float)(NTOK * DIM);
}

// ---------------------------------------------------------------------------
extern "C" void kernel_launch(void* const* d_in, const int* in_sizes, int n_in,
                              void* d_out, int out_size) {
    const float* z      = (const float*)d_in[0];
    const float* weight = (const float*)d_in[1];
    const float* ema_cs = (const float*)d_in[2];
    const float* ema_w  = (const float*)d_in[3];
    float* out = (float*)d_out;

    cudaFuncSetAttribute(coarse_mma_kernel,
                         cudaFuncAttributeMaxDynamicSharedMemorySize, SMEM_BYTES);

    __nv_bfloat16* dA = nullptr; cudaGetSymbolAddress((void**)&dA, g_A);
    __nv_bfloat16* dB = nullptr; cudaGetSymbolAddress((void**)&dB, g_B);

    init_kernel<<<(KCB * DIM + 255) / 256, 256>>>(ema_w, ema_cs, out);
    wnconv_kernel<<<KCB / 8, 256>>>(weight, dB);
    conv_kernel<<<(NTOK * DIM / 8 + 255) / 256, 256>>>(z, dA, NTOK * DIM / 8);
    coarse_mma_kernel<<<dim3(KCB / BN, NTOK / BM), 256, SMEM_BYTES>>>();
    scan_refine_scatter_kernel<<<NTOK, 256>>>(z, weight, out);
    nsum_kernel<<<1, 1024>>>(out);
    weight_kernel<<<(KCB * DIM + 255) / 256, 256>>>(out);
    gather_kernel<<<NTOK, 128>>>(z, out);
    finalize_kernel<<<1, 1>>>(out);
}

// round 17
// speedup vs baseline: 1.5623x; 1.5623x over previous
#include <cuda_runtime.h>
#include <cuda_bf16.h>
#include <cuda_fp16.h>
#include <cstdint>

#define NTOK 32768
#define DIM  512
#define KCB  8192

#define BM     128
#define BN     128
#define BK     64
#define NCHUNK (DIM / BK)         // 8
#define STAGES 3
#define TILE_BYTES (BM * BK * 2)  // 16384

#define THRESH   1.0f
#define CAND_MAX 256

// output layout (flat float32 concat, reference return order)
#define O_LOSS  ((size_t)0)
#define O_ZQ    ((size_t)1)
#define O_CODES ((size_t)(1 + (size_t)NTOK*DIM))
#define O_NW    ((size_t)(O_CODES + NTOK))
#define O_NCS   ((size_t)(O_NW + (size_t)KCB*DIM))
#define O_NEW   ((size_t)(O_NCS + KCB))

// ---- device scratch (static: no allocation allowed) ----
__device__ __align__(16) __nv_bfloat16 g_A[(size_t)NTOK * DIM];    // 32 MB
__device__ __align__(16) __nv_bfloat16 g_B[(size_t)KCB  * DIM];    // 8 MB
__device__ __align__(16) __half g_metric[(size_t)NTOK * KCB];      // 512 MB
__device__ int   g_codes[NTOK];
__device__ float g_wn[KCB];
__device__ float g_loss;
__device__ float g_nsum;

// ---------------------------------------------------------------------------
// PTX helpers (sm_80-era only: supported at base sm_103 PTX target)
// ---------------------------------------------------------------------------
__device__ __forceinline__ uint32_t smem_u32(const void* p) {
    uint32_t a;
    asm("{ .reg .u64 t; cvta.to.shared.u64 t, %1; cvt.u32.u64 %0, t; }" : "=r"(a) : "l"(p));
    return a;
}
__device__ __forceinline__ void cp16(uint32_t s, const void* g) {
    asm volatile("cp.async.cg.shared.global [%0], [%1], 16;" :: "r"(s), "l"(g));
}
#define CP_COMMIT() asm volatile("cp.async.commit_group;" ::: "memory")
#define CP_WAIT(n)  asm volatile("cp.async.wait_group %0;" :: "n"(n) : "memory")

__device__ __forceinline__ void ldsm4(uint32_t& r0, uint32_t& r1, uint32_t& r2, uint32_t& r3,
                                      uint32_t addr) {
    asm volatile("ldmatrix.sync.aligned.m8n8.x4.shared.b16 {%0,%1,%2,%3}, [%4];"
                 : "=r"(r0), "=r"(r1), "=r"(r2), "=r"(r3) : "r"(addr));
}
__device__ __forceinline__ void mma16816(float* d, uint32_t a0, uint32_t a1, uint32_t a2,
                                         uint32_t a3, uint32_t b0, uint32_t b1) {
    asm volatile(
        "mma.sync.aligned.m16n8k16.row.col.f32.bf16.bf16.f32 "
        "{%0,%1,%2,%3},{%4,%5,%6,%7},{%8,%9},{%0,%1,%2,%3};"
        : "+f"(d[0]), "+f"(d[1]), "+f"(d[2]), "+f"(d[3])
        : "r"(a0), "r"(a1), "r"(a2), "r"(a3), "r"(b0), "r"(b1));
}

// ---------------------------------------------------------------------------
// init
// ---------------------------------------------------------------------------
__global__ void init_kernel(const float* __restrict__ ema_w,
                            const float* __restrict__ ema_cs,
                            float* __restrict__ out) {
    int idx = blockIdx.x * blockDim.x + threadIdx.x;
    if (idx < KCB * DIM) out[O_NEW + idx] = 0.99f * ema_w[idx];
    if (idx < KCB)       out[O_NCS + idx] = 0.99f * ema_cs[idx];
    if (idx == 0) { g_loss = 0.0f; g_nsum = 0.0f; }
}

// ---------------------------------------------------------------------------
// wn + conv_w fused
// ---------------------------------------------------------------------------
__global__ void wnconv_kernel(const float* __restrict__ weight,
                              __nv_bfloat16* __restrict__ dstB) {
    int gw = (blockIdx.x * blockDim.x + threadIdx.x) >> 5;
    int lane = threadIdx.x & 31;
    if (gw >= KCB) return;
    const float4* row = (const float4*)(weight + (size_t)gw * DIM);
    __nv_bfloat16* drow = dstB + (size_t)gw * DIM;
    float s = 0.0f;
#pragma unroll
    for (int p = 0; p < 4; p++) {
        float4 v = row[p * 32 + lane];
        s += v.x * v.x + v.y * v.y + v.z * v.z + v.w * v.w;
        __nv_bfloat16 h[4] = {__float2bfloat16(v.x), __float2bfloat16(v.y),
                              __float2bfloat16(v.z), __float2bfloat16(v.w)};
        *(uint2*)(drow + p * 128 + lane * 4) = *(uint2*)h;
    }
#pragma unroll
    for (int o = 16; o > 0; o >>= 1) s += __shfl_xor_sync(0xffffffffu, s, o);
    if (lane == 0) g_wn[gw] = 0.5f * s;
}

// ---------------------------------------------------------------------------
// convert fp32 -> bf16 (z operand)
// ---------------------------------------------------------------------------
__global__ void conv_kernel(const float* __restrict__ src, __nv_bfloat16* __restrict__ dst,
                            int n8) {
    int idx = blockIdx.x * blockDim.x + threadIdx.x;
    if (idx >= n8) return;
    const float4* s4 = (const float4*)src + (size_t)idx * 2;
    float4 a = s4[0], b = s4[1];
    __nv_bfloat16 h[8] = {
        __float2bfloat16(a.x), __float2bfloat16(a.y), __float2bfloat16(a.z), __float2bfloat16(a.w),
        __float2bfloat16(b.x), __float2bfloat16(b.y), __float2bfloat16(b.z), __float2bfloat16(b.w)};
    *(uint4*)(dst + (size_t)idx * 8) = *(uint4*)h;
}

// ---------------------------------------------------------------------------
// coarse bf16 GEMM (R15 config: 3 stages, 2 CTAs/SM) with
//  - single __syncthreads per k-iteration (3-stage buffer distance proof)
//  - hoisted, precomputed ldmatrix fragment offsets
// ---------------------------------------------------------------------------
#define SMEM_WNS   (2 * STAGES * TILE_BYTES)           // 98304
#define SMEM_BYTES (SMEM_WNS + BN * 4)                 // 98816

__device__ __forceinline__ void load_chunk(uint32_t sb, const char* gA, const char* gB,
                                           int kc, int s, int tid) {
#pragma unroll
    for (int i = 0; i < 4; i++) {
        int idx = tid + i * 256;
        int row = idx >> 3, ch = idx & 7;
        uint32_t so = (uint32_t)(s * TILE_BYTES + row * 128 + ((ch ^ (row & 7)) << 4));
        cp16(sb + so, gA + (size_t)row * (DIM * 2) + (size_t)kc * (BK * 2) + ch * 16);
    }
#pragma unroll
    for (int i = 0; i < 4; i++) {
        int idx = tid + i * 256;
        int row = idx >> 3, ch = idx & 7;
        uint32_t so = (uint32_t)(STAGES * TILE_BYTES + s * TILE_BYTES + row * 128 +
                                 ((ch ^ (row & 7)) << 4));
        cp16(sb + so, gB + (size_t)row * (DIM * 2) + (size_t)kc * (BK * 2) + ch * 16);
    }
}

__global__ void __launch_bounds__(256, 2)
coarse_mma_kernel() {
    extern __shared__ __align__(128) unsigned char smem[];
    const uint32_t sb = smem_u32(smem);
    const int tid = threadIdx.x;
    const int lane = tid & 31, wid = tid >> 5;
    const int wm = wid & 3, wn = wid >> 2;
    const int n_tile = blockIdx.x, m_tile = blockIdx.y;

    float* wns_s = (float*)(smem + SMEM_WNS);
    if (tid < BN) wns_s[tid] = g_wn[n_tile * BN + tid];

    const char* gA = (const char*)g_A + (size_t)m_tile * BM * (DIM * 2);
    const char* gB = (const char*)g_B + (size_t)n_tile * BN * (DIM * 2);

    // precompute loop-invariant swizzled fragment offsets (per warp/lane)
    uint32_t aOff[4][2];   // [ks][mi]
    uint32_t bOff[4][4];   // [ks][p]
#pragma unroll
    for (int ks = 0; ks < 4; ks++) {
#pragma unroll
        for (int mi = 0; mi < 2; mi++) {
            int row = wm * 32 + mi * 16 + (lane & 15);
            int ch  = ks * 2 + (lane >> 4);
            aOff[ks][mi] = (uint32_t)(row * 128 + ((ch ^ (row & 7)) << 4));
        }
#pragma unroll
        for (int p = 0; p < 4; p++) {
            int l = lane & 7, sel = lane >> 3;
            int row = wn * 64 + p * 16 + (sel & 1) * 8 + l;
            int ch  = ks * 2 + (sel >> 1);
            bOff[ks][p] = (uint32_t)(row * 128 + ((ch ^ (row & 7)) << 4));
        }
    }

    float acc[2][8][4];
#pragma unroll
    for (int mi = 0; mi < 2; mi++)
#pragma unroll
        for (int ni = 0; ni < 8; ni++)
#pragma unroll
            for (int j = 0; j < 4; j++) acc[mi][ni][j] = 0.0f;

#pragma unroll
    for (int i = 0; i < STAGES - 1; i++) {
        load_chunk(sb, gA, gB, i, i, tid);
        CP_COMMIT();
    }

    for (int kc = 0; kc < NCHUNK; kc++) {
        const int s = kc % STAGES;
        CP_WAIT(STAGES - 2);
        __syncthreads();   // single sync: orders prev compute before prefetch AND
                           // makes this chunk's cp.async data CTA-visible
        const int pf = kc + STAGES - 1;
        if (pf < NCHUNK) load_chunk(sb, gA, gB, pf, pf % STAGES, tid);
        CP_COMMIT();

        const uint32_t aBase = sb + s * TILE_BYTES;
        const uint32_t bBase = sb + (STAGES + s) * TILE_BYTES;
#pragma unroll
        for (int ks = 0; ks < 4; ks++) {
            uint32_t a[2][4];
#pragma unroll
            for (int mi = 0; mi < 2; mi++)
                ldsm4(a[mi][0], a[mi][1], a[mi][2], a[mi][3], aBase + aOff[ks][mi]);
            uint32_t b[8][2];
#pragma unroll
            for (int p = 0; p < 4; p++) {
                uint32_t r0, r1, r2, r3;
                ldsm4(r0, r1, r2, r3, bBase + bOff[ks][p]);
                b[2 * p][0] = r0; b[2 * p][1] = r2;
                b[2 * p + 1][0] = r1; b[2 * p + 1][1] = r3;
            }
#pragma unroll
            for (int mi = 0; mi < 2; mi++)
#pragma unroll
                for (int ni = 0; ni < 8; ni++)
                    mma16816(acc[mi][ni], a[mi][0], a[mi][1], a[mi][2], a[mi][3],
                             b[ni][0], b[ni][1]);
        }
    }
    __syncthreads();   // final: protect smem (epilogue reuses nothing, but cheap)

    // epilogue: store coarse metric tile as fp16 (half2, 4B-aligned)
#pragma unroll
    for (int mi = 0; mi < 2; mi++) {
#pragma unroll
        for (int r = 0; r < 2; r++) {
            int token = m_tile * BM + wm * 32 + mi * 16 + r * 8 + (lane >> 2);
            __half* rowp = g_metric + (size_t)token * KCB + n_tile * BN;
#pragma unroll
            for (int ni = 0; ni < 8; ni++) {
                int n0 = wn * 64 + ni * 8 + (lane & 3) * 2;
                __half2 v = __floats2half2_rn(acc[mi][ni][r * 2 + 0] - wns_s[n0],
                                              acc[mi][ni][r * 2 + 1] - wns_s[n0 + 1]);
                *(__half2*)(rowp + n0) = v;
            }
        }
    }
}

// ---------------------------------------------------------------------------
// scan + exact refine + fused scatter (validated R15)
// ---------------------------------------------------------------------------
__global__ void __launch_bounds__(256)
scan_refine_scatter_kernel(const float* __restrict__ z, const float* __restrict__ weight,
                           float* __restrict__ out) {
    __shared__ __half met[KCB];         // 16 KB
    __shared__ float wred[8];
    __shared__ int   cand[CAND_MAX];
    __shared__ int   ccount;
    __shared__ float wbest[8];
    __shared__ int   wbidx[8];
    __shared__ int   s_code;

    const int token = blockIdx.x;
    const int tid = threadIdx.x;
    const int lane = tid & 31, wid = tid >> 5;

    const float4* src = (const float4*)(g_metric + (size_t)token * KCB);
    float lmax = -3.4e38f;
#pragma unroll
    for (int i = 0; i < 4; i++) {
        float4 v = src[tid + i * 256];
        ((float4*)met)[tid + i * 256] = v;
        const __half2* h2 = (const __half2*)&v;
#pragma unroll
        for (int j = 0; j < 4; j++) {
            float2 f = __half22float2(h2[j]);
            lmax = fmaxf(lmax, fmaxf(f.x, f.y));
        }
    }
#pragma unroll
    for (int o = 16; o > 0; o >>= 1) lmax = fmaxf(lmax, __shfl_xor_sync(0xffffffffu, lmax, o));
    if (lane == 0) wred[wid] = lmax;
    if (tid == 0) ccount = 0;
    __syncthreads();
    float gmax = wred[0];
#pragma unroll
    for (int w = 1; w < 8; w++) gmax = fmaxf(gmax, wred[w]);
    const float thresh = gmax - THRESH;

    for (int i = tid; i < KCB; i += 256) {
        if (__half2float(met[i]) >= thresh) {
            int p = atomicAdd(&ccount, 1);
            if (p < CAND_MAX) cand[p] = i;
        }
    }
    __syncthreads();
    int nc = ccount;
    if (nc > CAND_MAX) nc = CAND_MAX;

    const float4* z4 = (const float4*)(z + (size_t)token * DIM);
    float4 zw[4];
#pragma unroll
    for (int i = 0; i < 4; i++) zw[i] = z4[lane + 32 * i];

    float best = -3.4e38f;
    int bidx = KCB;
    for (int c = wid; c < nc; c += 8) {
        int k = cand[c];
        const float4* w4 = (const float4*)(weight + (size_t)k * DIM);
        float s = 0.0f;
#pragma unroll
        for (int i = 0; i < 4; i++) {
            float4 wv = w4[lane + 32 * i];
            s += zw[i].x * wv.x + zw[i].y * wv.y + zw[i].z * wv.z + zw[i].w * wv.w;
        }
#pragma unroll
        for (int o = 16; o > 0; o >>= 1) s += __shfl_xor_sync(0xffffffffu, s, o);
        float mex = s - g_wn[k];
        if (mex > best || (mex == best && k < bidx)) { best = mex; bidx = k; }
    }
    if (lane == 0) { wbest[wid] = best; wbidx[wid] = bidx; }
    __syncthreads();
    if (tid == 0) {
        float bb = wbest[0];
        int bi = wbidx[0];
#pragma unroll
        for (int w = 1; w < 8; w++) {
            float v = wbest[w];
            int k = wbidx[w];
            if (v > bb || (v == bb && k < bi)) { bb = v; bi = k; }
        }
        s_code = bi;
        g_codes[token] = bi;
        out[O_CODES + token] = (float)bi;
        atomicAdd(out + O_NCS + bi, 0.01f);
    }
    __syncthreads();

    const int code = s_code;
    float* dst = out + O_NEW + (size_t)code * DIM;
    const float2 zv = ((const float2*)(z + (size_t)token * DIM))[tid];
    atomicAdd(dst + 2 * tid,     0.01f * zv.x);
    atomicAdd(dst + 2 * tid + 1, 0.01f * zv.y);
}

// ---------------------------------------------------------------------------
// nsum / weight / gather / finalize (validated R1..R15)
// ---------------------------------------------------------------------------
__global__ void nsum_kernel(const float* __restrict__ out) {
    __shared__ float red[1024];
    int tid = threadIdx.x;
    float s = 0.0f;
    for (int i = tid; i < KCB; i += 1024) s += out[O_NCS + i];
    red[tid] = s;
    __syncthreads();
    for (int o = 512; o > 0; o >>= 1) {
        if (tid < o) red[tid] += red[tid + o];
        __syncthreads();
    }
    if (tid == 0) g_nsum = red[0];
}

__global__ void weight_kernel(float* __restrict__ out) {
    int idx = blockIdx.x * blockDim.x + threadIdx.x;
    if (idx >= KCB * DIM) return;
    int k = idx >> 9;
    float n = g_nsum;
    float cs = (out[O_NCS + k] + 1e-5f) / (n + KCB * 1e-5f) * n;
    out[O_NW + idx] = out[O_NEW + idx] / cs;
}

__global__ void gather_kernel(const float* __restrict__ z, float* __restrict__ out) {
    __shared__ float red[128];
    int token = blockIdx.x, tid = threadIdx.x;
    int code = g_codes[token];
    const float* wr = out + O_NW + (size_t)code * DIM;
    const float* zr = z + (size_t)token * DIM;
    float* oq = out + O_ZQ + (size_t)token * DIM;
    float ls = 0.0f;
#pragma unroll
    for (int i = 0; i < 4; i++) {
        int d = i * 128 + tid;
        float w = wr[d], v = zr[d];
        float t = w - v;
        oq[d] = v + t;
        ls += t * t;
    }
    red[tid] = ls;
    __syncthreads();
    for (int o = 64; o > 0; o >>= 1) {
        if (tid < o) red[tid] += red[tid + o];
        __syncthreads();
    }
    if (tid == 0) atomicAdd(&g_loss, red[0]);
}

__global__ void finalize_kernel(float* __restrict__ out) {
    out[O_LOSS] = 0.25f * g_loss / (float)(NTOK * DIM);
}

// ---------------------------------------------------------------------------
extern "C" void kernel_launch(void* const* d_in, const int* in_sizes, int n_in,
                              void* d_out, int out_size) {
    const float* z      = (const float*)d_in[0];
    const float* weight = (const float*)d_in[1];
    const float* ema_cs = (const float*)d_in[2];
    const float* ema_w  = (const float*)d_in[3];
    float* out = (float*)d_out;

    cudaFuncSetAttribute(coarse_mma_kernel,
                         cudaFuncAttributeMaxDynamicSharedMemorySize, SMEM_BYTES);

    __nv_bfloat16* dA = nullptr; cudaGetSymbolAddress((void**)&dA, g_A);
    __nv_bfloat16* dB = nullptr; cudaGetSymbolAddress((void**)&dB, g_B);

    init_kernel<<<(KCB * DIM + 255) / 256, 256>>>(ema_w, ema_cs, out);
    wnconv_kernel<<<KCB / 8, 256>>>(weight, dB);
    conv_kernel<<<(NTOK * DIM / 8 + 255) / 256, 256>>>(z, dA, NTOK * DIM / 8);
    coarse_mma_kernel<<<dim3(KCB / BN, NTOK / BM), 256, SMEM_BYTES>>>();
    scan_refine_scatter_kernel<<<NTOK, 256>>>(z, weight, out);
    nsum_kernel<<<1, 1024>>>(out);
    weight_kernel<<<(KCB * DIM + 255) / 256, 256>>>(out);
    gather_kernel<<<NTOK, 128>>>(z, out);
    finalize_kernel<<<1, 1>>>(out);
}